// round 3
// baseline (speedup 1.0000x reference)
#include <cuda_runtime.h>
#include <cstdint>

// Problem constants
#define B_     8
#define Q_     500
#define C_     256
#define S_     8
#define NP_    2
#define SSCALE 0.077f
#define NPIX_  8500

__constant__ int c_lvl_h[4]  = {80, 40, 20, 10};
__constant__ int c_lvl_w[4]  = {80, 40, 20, 10};
__constant__ int c_lvl_st[4] = {0, 6400, 8000, 8400};

__global__ __launch_bounds__(256)
void decoder_kernel(const float* __restrict__ ref_polys,
                    const int*   __restrict__ ref_levels,
                    const float* __restrict__ memory,
                    const float* __restrict__ W1,
                    const float* __restrict__ b1,
                    const float* __restrict__ W2,
                    const float* __restrict__ b2,
                    float* __restrict__ out)
{
    __shared__ float  embT[C_ * S_];        // [c][s], 8 KB, transposed for f32x2 pairs
    __shared__ int    s_idx[S_][4];         // absolute element offsets of 4 corners
    __shared__ float  s_w[S_][4];           // bilinear weights (validity folded in)
    __shared__ float  s_spt[S_][2];         // sampling points in [-1,1]
    __shared__ float  wred[8][32];          // cross-warp reduction scratch

    const int bq  = blockIdx.x;             // 0 .. B*Q-1
    const int b   = bq / Q_;
    const int tid = threadIdx.x;

    // ---------- stage 1: sampling-point + corner precompute (threads 0..7) ----------
    if (tid < S_) {
        const int s = tid;
        const float lam = (float)s * (1.0f / 7.0f);
        const float* rp = ref_polys + (size_t)bq * 8;
        float px = ((rp[0]*lam + rp[1])*lam + rp[2])*lam + rp[3];
        float py = ((rp[4]*lam + rp[5])*lam + rp[6])*lam + rp[7];
        float sx = 2.0f*(px - 0.5f);
        float sy = 2.0f*(py - 0.5f);
        s_spt[s][0] = sx;
        s_spt[s][1] = sy;

        const int lvl = ref_levels[bq];
        const int H  = c_lvl_h[lvl];
        const int W  = c_lvl_w[lvl];
        const int st = c_lvl_st[lvl];
        const int base = b * NPIX_ + st;

        float gx = (sx + 1.0f) * 0.5f * (float)W - 0.5f;
        float gy = (sy + 1.0f) * 0.5f * (float)H - 0.5f;
        float x0 = floorf(gx), y0 = floorf(gy);
        float wx1 = gx - x0, wx0 = 1.0f - wx1;
        float wy1 = gy - y0, wy0 = 1.0f - wy1;

        #pragma unroll
        for (int k = 0; k < 4; k++) {
            float xf = (k & 1) ? (x0 + 1.0f) : x0;
            float yf = (k & 2) ? (y0 + 1.0f) : y0;
            float wx = (k & 1) ? wx1 : wx0;
            float wy = (k & 2) ? wy1 : wy0;
            bool valid = (xf >= 0.0f) && (xf <= (float)(W-1)) &&
                         (yf >= 0.0f) && (yf <= (float)(H-1));
            int xc = (int)fminf(fmaxf(xf, 0.0f), (float)(W-1));
            int yc = (int)fminf(fmaxf(yf, 0.0f), (float)(H-1));
            s_idx[s][k] = (base + yc * W + xc) * C_;
            s_w[s][k]   = valid ? (wy * wx) : 0.0f;
        }
    }
    __syncthreads();

    // ---------- stage 2: bilinear gather -> emb (one channel per thread) ----------
    {
        const int c = tid;
        float e[S_];
        #pragma unroll
        for (int s = 0; s < S_; s++) {
            int4   id = *(const int4*  )&s_idx[s][0];   // smem broadcast
            float4 w  = *(const float4*)&s_w[s][0];
            float v =  w.x * __ldg(memory + id.x + c);
            v = fmaf(w.y, __ldg(memory + id.y + c), v);
            v = fmaf(w.z, __ldg(memory + id.z + c), v);
            v = fmaf(w.w, __ldg(memory + id.w + c), v);
            e[s] = v;
        }
        // transposed store: embT[c][0..7]
        *(float4*)&embT[c * S_ + 0] = make_float4(e[0], e[1], e[2], e[3]);
        *(float4*)&embT[c * S_ + 4] = make_float4(e[4], e[5], e[6], e[7]);
    }
    __syncthreads();

    // ---------- stage 3: GEMM1  h[s][j] = tanh(sum_c emb[s][c]*W1[c][j] + b1[j]) ----
    // One output column j per thread; S dimension packed in f32x2 (FFMA2).
    const int j = tid;
    unsigned long long acc0 = 0ull, acc1 = 0ull, acc2 = 0ull, acc3 = 0ull;
    {
        const float* w1p = W1 + j;
        #pragma unroll 8
        for (int cc = 0; cc < C_; cc++) {
            float w = __ldg(w1p + (cc << 8));
            unsigned long long wp;
            asm("mov.b64 %0, {%1, %1};" : "=l"(wp) : "f"(w));
            const unsigned long long* ep =
                (const unsigned long long*)&embT[cc * S_];
            unsigned long long e01 = ep[0];
            unsigned long long e23 = ep[1];
            unsigned long long e45 = ep[2];
            unsigned long long e67 = ep[3];
            asm("fma.rn.f32x2 %0, %1, %2, %0;" : "+l"(acc0) : "l"(e01), "l"(wp));
            asm("fma.rn.f32x2 %0, %1, %2, %0;" : "+l"(acc1) : "l"(e23), "l"(wp));
            asm("fma.rn.f32x2 %0, %1, %2, %0;" : "+l"(acc2) : "l"(e45), "l"(wp));
            asm("fma.rn.f32x2 %0, %1, %2, %0;" : "+l"(acc3) : "l"(e67), "l"(wp));
        }
    }

    float h[S_];
    {
        const float bj = __ldg(b1 + j);
        float lo, hi;
        asm("mov.b64 {%0, %1}, %2;" : "=f"(lo), "=f"(hi) : "l"(acc0));
        h[0] = tanhf(lo + bj); h[1] = tanhf(hi + bj);
        asm("mov.b64 {%0, %1}, %2;" : "=f"(lo), "=f"(hi) : "l"(acc1));
        h[2] = tanhf(lo + bj); h[3] = tanhf(hi + bj);
        asm("mov.b64 {%0, %1}, %2;" : "=f"(lo), "=f"(hi) : "l"(acc2));
        h[4] = tanhf(lo + bj); h[5] = tanhf(hi + bj);
        asm("mov.b64 {%0, %1}, %2;" : "=f"(lo), "=f"(hi) : "l"(acc3));
        h[6] = tanhf(lo + bj); h[7] = tanhf(hi + bj);
    }

    // ---------- stage 4: GEMM2 off[s][k] = sum_j h[s][j]*W2[j][k] (k = 0..3) -------
    float p[32];
    {
        float4 w2 = *(const float4*)(W2 + j * 4);
        #pragma unroll
        for (int s = 0; s < S_; s++) {
            p[s*4 + 0] = h[s] * w2.x;
            p[s*4 + 1] = h[s] * w2.y;
            p[s*4 + 2] = h[s] * w2.z;
            p[s*4 + 3] = h[s] * w2.w;
        }
    }
    // warp reduce (all 32 values -> lane 0)
    #pragma unroll
    for (int off = 16; off > 0; off >>= 1) {
        #pragma unroll
        for (int v = 0; v < 32; v++)
            p[v] += __shfl_down_sync(0xffffffffu, p[v], off);
    }
    const int warp = tid >> 5;
    const int lane = tid & 31;
    if (lane == 0) {
        #pragma unroll
        for (int v = 0; v < 32; v++) wred[warp][v] = p[v];
    }
    __syncthreads();

    // ---------- stage 5: epilogue (threads 0..31 each own one (s,k)) ---------------
    if (tid < 32) {
        float sum = 0.0f;
        #pragma unroll
        for (int w = 0; w < 8; w++) sum += wred[w][tid];
        const int s  = tid >> 2;
        const int k  = tid & 3;      // k = np*2 + xy
        const int np = k >> 1;
        const int xy = k & 1;
        float off = SSCALE * tanhf(sum + __ldg(b2 + k));
        out[((size_t)bq * (S_ * NP_) + (s * NP_ + np)) * 2 + xy] = off + s_spt[s][xy];
    }
}

extern "C" void kernel_launch(void* const* d_in, const int* in_sizes, int n_in,
                              void* d_out, int out_size)
{
    const float* ref_polys  = (const float*)d_in[0];
    const int*   ref_levels = (const int*  )d_in[1];
    const float* memory     = (const float*)d_in[2];
    const float* W1         = (const float*)d_in[3];
    const float* b1         = (const float*)d_in[4];
    const float* W2         = (const float*)d_in[5];
    const float* b2         = (const float*)d_in[6];
    float* out = (float*)d_out;

    decoder_kernel<<<B_ * Q_, 256>>>(ref_polys, ref_levels, memory,
                                     W1, b1, W2, b2, out);
}

// round 5
// speedup vs baseline: 1.6495x; 1.6495x over previous
#include <cuda_runtime.h>
#include <cstdint>

typedef unsigned long long ull;

// Problem constants
#define B_     8
#define Q_     500
#define C_     256
#define S_     8
#define NP_    2
#define SSCALE 0.077f
#define NPIX_  8500
#define QPB    4      // queries per block

__constant__ int c_lvl_h[4]  = {80, 40, 20, 10};
__constant__ int c_lvl_st[4] = {0, 6400, 8000, 8400};

__device__ __forceinline__ float fast_tanh(float x) {
    float y;
    asm("tanh.approx.f32 %0, %1;" : "=f"(y) : "f"(x));
    return y;
}

__global__ __launch_bounds__(256)
void decoder_kernel(const float* __restrict__ ref_polys,
                    const int*   __restrict__ ref_levels,
                    const float* __restrict__ memory,
                    const float* __restrict__ W1,
                    const float* __restrict__ b1,
                    const float* __restrict__ W2,
                    const float* __restrict__ b2,
                    float* __restrict__ out)
{
    __shared__ __align__(16) float embT[QPB][C_ * S_];   // 32 KB, [q][c][s]
    __shared__ int   s_idx[QPB][S_][4];
    __shared__ float s_w[QPB][S_][4];
    __shared__ float s_spt[QPB][S_][2];
    __shared__ float wred[8][32];

    const int tid = threadIdx.x;
    const int bq0 = blockIdx.x * QPB;

    // ---------- stage 1: sampling points + bilinear corners (threads 0..31) -------
    if (tid < QPB * S_) {
        const int qi = tid >> 3;
        const int s  = tid & 7;
        const int bq = bq0 + qi;
        const int b  = bq / Q_;
        const float lam = (float)s * (1.0f / 7.0f);
        const float* rp = ref_polys + (size_t)bq * 8;
        float px = ((rp[0]*lam + rp[1])*lam + rp[2])*lam + rp[3];
        float py = ((rp[4]*lam + rp[5])*lam + rp[6])*lam + rp[7];
        float sx = 2.0f*(px - 0.5f);
        float sy = 2.0f*(py - 0.5f);
        s_spt[qi][s][0] = sx;
        s_spt[qi][s][1] = sy;

        const int lvl = ref_levels[bq];
        const int H  = c_lvl_h[lvl];
        const int W  = H;                       // square levels
        const int st = c_lvl_st[lvl];
        const int base = b * NPIX_ + st;

        float gx = (sx + 1.0f) * 0.5f * (float)W - 0.5f;
        float gy = (sy + 1.0f) * 0.5f * (float)H - 0.5f;
        float x0 = floorf(gx), y0 = floorf(gy);
        float wx1 = gx - x0, wx0 = 1.0f - wx1;
        float wy1 = gy - y0, wy0 = 1.0f - wy1;

        #pragma unroll
        for (int k = 0; k < 4; k++) {
            float xf = (k & 1) ? (x0 + 1.0f) : x0;
            float yf = (k & 2) ? (y0 + 1.0f) : y0;
            float wx = (k & 1) ? wx1 : wx0;
            float wy = (k & 2) ? wy1 : wy0;
            bool valid = (xf >= 0.0f) && (xf <= (float)(W-1)) &&
                         (yf >= 0.0f) && (yf <= (float)(H-1));
            int xc = (int)fminf(fmaxf(xf, 0.0f), (float)(W-1));
            int yc = (int)fminf(fmaxf(yf, 0.0f), (float)(H-1));
            s_idx[qi][s][k] = (base + yc * W + xc) * C_;
            s_w[qi][s][k]   = valid ? (wy * wx) : 0.0f;
        }
    }
    __syncthreads();

    // ---------- stage 2: bilinear gather for all 4 queries (c = tid) --------------
    {
        const int c = tid;
        #pragma unroll
        for (int qi = 0; qi < QPB; qi++) {
            float e[S_];
            #pragma unroll
            for (int s = 0; s < S_; s++) {
                int4   id = *(const int4*  )&s_idx[qi][s][0];
                float4 w  = *(const float4*)&s_w[qi][s][0];
                float v =  w.x * __ldg(memory + id.x + c);
                v = fmaf(w.y, __ldg(memory + id.y + c), v);
                v = fmaf(w.z, __ldg(memory + id.z + c), v);
                v = fmaf(w.w, __ldg(memory + id.w + c), v);
                e[s] = v;
            }
            *(float4*)&embT[qi][c * S_ + 0] = make_float4(e[0], e[1], e[2], e[3]);
            *(float4*)&embT[qi][c * S_ + 4] = make_float4(e[4], e[5], e[6], e[7]);
        }
    }
    __syncthreads();

    // ---------- stage 3: GEMM1, 4 columns per thread, f32x2 over S ----------------
    // thread -> query qi = tid>>6, columns j = 4*(tid&63) + u, u=0..3
    const int qi = tid >> 6;
    const int jb = (tid & 63) << 2;

    ull acc[4][4];
    #pragma unroll
    for (int u = 0; u < 4; u++)
        #pragma unroll
        for (int pr = 0; pr < 4; pr++) acc[u][pr] = 0ull;

    {
        const float* w1p = W1 + jb;
        const ull* ep = (const ull*)&embT[qi][0];
        #pragma unroll 4
        for (int cc = 0; cc < C_; cc++) {
            float4 w = __ldg((const float4*)(w1p + (cc << 8)));
            ull wp0, wp1, wp2, wp3;
            asm("mov.b64 %0, {%1, %1};" : "=l"(wp0) : "f"(w.x));
            asm("mov.b64 %0, {%1, %1};" : "=l"(wp1) : "f"(w.y));
            asm("mov.b64 %0, {%1, %1};" : "=l"(wp2) : "f"(w.z));
            asm("mov.b64 %0, {%1, %1};" : "=l"(wp3) : "f"(w.w));
            ulonglong2 ea = *(const ulonglong2*)(ep + cc * 4);
            ulonglong2 eb = *(const ulonglong2*)(ep + cc * 4 + 2);
            #pragma unroll
            for (int u = 0; u < 4; u++) {
                ull wp = (u == 0) ? wp0 : (u == 1) ? wp1 : (u == 2) ? wp2 : wp3;
                asm("fma.rn.f32x2 %0, %1, %2, %0;" : "+l"(acc[u][0]) : "l"(ea.x), "l"(wp));
                asm("fma.rn.f32x2 %0, %1, %2, %0;" : "+l"(acc[u][1]) : "l"(ea.y), "l"(wp));
                asm("fma.rn.f32x2 %0, %1, %2, %0;" : "+l"(acc[u][2]) : "l"(eb.x), "l"(wp));
                asm("fma.rn.f32x2 %0, %1, %2, %0;" : "+l"(acc[u][3]) : "l"(eb.y), "l"(wp));
            }
        }
    }

    // ---------- stage 4: bias + tanh + GEMM2 partials (per thread) ----------------
    float p[32];
    #pragma unroll
    for (int v = 0; v < 32; v++) p[v] = 0.0f;
    {
        float4 bj = __ldg((const float4*)(b1 + jb));
        float bja[4] = {bj.x, bj.y, bj.z, bj.w};
        #pragma unroll
        for (int u = 0; u < 4; u++) {
            float hh[8];
            #pragma unroll
            for (int pr = 0; pr < 4; pr++) {
                float lo, hi;
                asm("mov.b64 {%0, %1}, %2;" : "=f"(lo), "=f"(hi) : "l"(acc[u][pr]));
                hh[pr*2 + 0] = fast_tanh(lo + bja[u]);
                hh[pr*2 + 1] = fast_tanh(hi + bja[u]);
            }
            float4 w2 = __ldg((const float4*)(W2 + (size_t)(jb + u) * 4));
            #pragma unroll
            for (int s = 0; s < 8; s++) {
                p[s*4 + 0] = fmaf(hh[s], w2.x, p[s*4 + 0]);
                p[s*4 + 1] = fmaf(hh[s], w2.y, p[s*4 + 1]);
                p[s*4 + 2] = fmaf(hh[s], w2.z, p[s*4 + 2]);
                p[s*4 + 3] = fmaf(hh[s], w2.w, p[s*4 + 3]);
            }
        }
    }

    // ---------- stage 5: warp reduce-scatter (31 shuffles, lane l ends with v=l) --
    const int lane = tid & 31;
    #pragma unroll
    for (int m = 16; m >= 1; m >>= 1) {
        #pragma unroll
        for (int v = 0; v < m; v++) {
            float send = (lane & m) ? p[v] : p[v + m];
            float recv = __shfl_xor_sync(0xffffffffu, send, m);
            p[v] = ((lane & m) ? p[v + m] : p[v]) + recv;
        }
    }
    wred[tid >> 5][lane] = p[0];
    __syncthreads();

    // ---------- stage 6: combine two warps per query + epilogue -------------------
    if (tid < 128) {
        const int q2 = tid >> 5;         // query within block
        const int v  = tid & 31;         // = s*4 + k
        float sum = wred[q2*2][v] + wred[q2*2 + 1][v];
        const int s  = v >> 2;
        const int k  = v & 3;            // k = np*2 + xy
        const int np = k >> 1;
        const int xy = k & 1;
        float off = SSCALE * fast_tanh(sum + __ldg(b2 + k));
        const int bq = bq0 + q2;
        out[((size_t)bq * (S_ * NP_) + (s * NP_ + np)) * 2 + xy] = off + s_spt[q2][s][xy];
    }
}

extern "C" void kernel_launch(void* const* d_in, const int* in_sizes, int n_in,
                              void* d_out, int out_size)
{
    const float* ref_polys  = (const float*)d_in[0];
    const int*   ref_levels = (const int*  )d_in[1];
    const float* memory     = (const float*)d_in[2];
    const float* W1         = (const float*)d_in[3];
    const float* b1         = (const float*)d_in[4];
    const float* W2         = (const float*)d_in[5];
    const float* b2         = (const float*)d_in[6];
    float* out = (float*)d_out;

    decoder_kernel<<<(B_ * Q_) / QPB, 256>>>(ref_polys, ref_levels, memory,
                                             W1, b1, W2, b2, out);
}

// round 7
// speedup vs baseline: 3.1062x; 1.8831x over previous
#include <cuda_runtime.h>
#include <cuda_bf16.h>
#include <cstdint>

#define B_     8
#define Q_     500
#define C_     256
#define S_     8
#define QPB    8
#define ROWS   64           // QPB * S_
#define NPIX_  8500
#define SSCALE 0.077f

// dynamic smem layout (bytes)
#define SM_AHI   0          // 64 x 256 bf16 = 32768
#define SM_ALO   32768      // 32768
#define SM_IDX   65536      // 64*4 int   = 1024
#define SM_WB    66560      // 64*4 float = 1024
#define SM_SPT   67584      // 64*2 float = 512
#define SM_B1    68096      // 256 float  = 1024
#define SM_W2    69120      // 256 float4 = 4096
#define SM_PART  73216      // 4 x 64 float4 = 4096
#define SM_TOTAL 77824

__constant__ int c_lvl_h[4]  = {80, 40, 20, 10};
__constant__ int c_lvl_st[4] = {0, 6400, 8000, 8400};

// W1 pre-packed into mma.sync B-fragment order:
// uint4 per (k16 chunk kk, n8 tile nn, lane): {bh0, bh1, bl0, bl1}
__device__ __align__(16) uint4 g_w1b[16 * 32 * 32];

__device__ __forceinline__ float fast_tanh(float x) {
    float y; asm("tanh.approx.f32 %0, %1;" : "=f"(y) : "f"(x)); return y;
}
__device__ __forceinline__ uint32_t smem_u32(const void* p) {
    uint32_t a;
    asm("{ .reg .u64 t; cvta.to.shared.u64 t, %1; cvt.u32.u64 %0, t; }" : "=r"(a) : "l"(p));
    return a;
}
__device__ __forceinline__ void ldmatrix_x4(uint32_t& r0, uint32_t& r1,
                                            uint32_t& r2, uint32_t& r3, uint32_t addr) {
    asm volatile("ldmatrix.sync.aligned.m8n8.x4.shared.b16 {%0,%1,%2,%3}, [%4];"
                 : "=r"(r0), "=r"(r1), "=r"(r2), "=r"(r3) : "r"(addr));
}
__device__ __forceinline__ void mma_bf16(float* d, const uint32_t* a,
                                         uint32_t b0, uint32_t b1) {
    asm volatile("mma.sync.aligned.m16n8k16.row.col.f32.bf16.bf16.f32 "
                 "{%0,%1,%2,%3}, {%4,%5,%6,%7}, {%8,%9}, {%0,%1,%2,%3};"
                 : "+f"(d[0]), "+f"(d[1]), "+f"(d[2]), "+f"(d[3])
                 : "r"(a[0]), "r"(a[1]), "r"(a[2]), "r"(a[3]), "r"(b0), "r"(b1));
}

// ---- prep: W1 fp32 [K=256][N=256] -> bf16 hi/lo in B-fragment order ----------
__global__ void prep_w1(const float* __restrict__ W1) {
    const int k = blockIdx.x;    // K row
    const int n = threadIdx.x;   // N col
    float v = __ldg(W1 + k * 256 + n);
    __nv_bfloat16 hb = __float2bfloat16(v);
    float hf = __bfloat162float(hb);
    __nv_bfloat16 lb = __float2bfloat16(v - hf);

    const int kk = k >> 4, kr = k & 15;
    const int nn = n >> 3, ncell = n & 7;
    const int lane = ncell * 4 + ((kr & 7) >> 1);
    const int r = kr >> 3;       // which reg (k rows 0-7 vs 8-15)
    const int h = kr & 1;        // halfword within reg
    uint16_t* dst = (uint16_t*)g_w1b;
    const int base = (((kk * 32 + nn) * 32 + lane) * 4);
    dst[(base + r)     * 2 + h] = *(uint16_t*)&hb;   // hi regs: x,y
    dst[(base + 2 + r) * 2 + h] = *(uint16_t*)&lb;   // lo regs: z,w
}

// ---- main --------------------------------------------------------------------
__global__ __launch_bounds__(256)
void decoder_kernel(const float* __restrict__ ref_polys,
                    const int*   __restrict__ ref_levels,
                    const float* __restrict__ memory,
                    const float* __restrict__ b1,
                    const float* __restrict__ W2,
                    const float* __restrict__ b2,
                    float* __restrict__ out)
{
    extern __shared__ __align__(16) char smem[];
    const uint32_t sb = smem_u32(smem);
    const int tid  = threadIdx.x;
    const int wid  = tid >> 5;
    const int lane = tid & 31;
    const int bq0  = blockIdx.x * QPB;

    int*    s_idx  = (int*)   (smem + SM_IDX);
    float*  s_w    = (float*) (smem + SM_WB);
    float*  s_spt  = (float*) (smem + SM_SPT);
    float*  b1s    = (float*) (smem + SM_B1);
    float4* w2s    = (float4*)(smem + SM_W2);
    float4* s_part = (float4*)(smem + SM_PART);

    // ---- stage 1: sampling points + bilinear corners (threads 0..63) ----
    if (tid < ROWS) {
        const int qi = tid >> 3, s = tid & 7;
        const int bq = bq0 + qi;
        const int b  = bq / Q_;
        const float lam = (float)s * (1.0f / 7.0f);
        const float* rp = ref_polys + (size_t)bq * 8;
        float px = ((rp[0]*lam + rp[1])*lam + rp[2])*lam + rp[3];
        float py = ((rp[4]*lam + rp[5])*lam + rp[6])*lam + rp[7];
        float sx = 2.0f*(px - 0.5f), sy = 2.0f*(py - 0.5f);
        s_spt[tid*2 + 0] = sx;
        s_spt[tid*2 + 1] = sy;

        const int lvl = ref_levels[bq];
        const int H = c_lvl_h[lvl], W = H;
        const int base = b * NPIX_ + c_lvl_st[lvl];
        float gx = (sx + 1.0f) * 0.5f * (float)W - 0.5f;
        float gy = (sy + 1.0f) * 0.5f * (float)H - 0.5f;
        float x0 = floorf(gx), y0 = floorf(gy);
        float wx1 = gx - x0, wx0 = 1.0f - wx1;
        float wy1 = gy - y0, wy0 = 1.0f - wy1;
        #pragma unroll
        for (int k = 0; k < 4; k++) {
            float xf = (k & 1) ? (x0 + 1.0f) : x0;
            float yf = (k & 2) ? (y0 + 1.0f) : y0;
            float wx = (k & 1) ? wx1 : wx0;
            float wy = (k & 2) ? wy1 : wy0;
            bool valid = (xf >= 0.0f) && (xf <= (float)(W-1)) &&
                         (yf >= 0.0f) && (yf <= (float)(H-1));
            int xc = (int)fminf(fmaxf(xf, 0.0f), (float)(W-1));
            int yc = (int)fminf(fmaxf(yf, 0.0f), (float)(H-1));
            s_idx[tid*4 + k] = (base + yc * W + xc) * C_;
            s_w[tid*4 + k]   = valid ? (wy * wx) : 0.0f;
        }
    }
    b1s[tid] = __ldg(b1 + tid);
    w2s[tid] = __ldg((const float4*)W2 + tid);
    __syncthreads();

    // ---- stage 2: gather -> A_hi / A_lo bf16, XOR-swizzled rows of 512B ----
    {
        const int p2   = tid & 127;     // channel pair 0..127
        const int half = tid >> 7;      // row half
        #pragma unroll 4
        for (int r = 0; r < 32; r++) {
            const int m = half * 32 + r;
            int4   id = *(const int4*  )(s_idx + m * 4);
            float4 w  = *(const float4*)(s_w   + m * 4);
            float2 v0 = __ldg((const float2*)(memory + id.x) + p2);
            float2 v1 = __ldg((const float2*)(memory + id.y) + p2);
            float2 v2 = __ldg((const float2*)(memory + id.z) + p2);
            float2 v3 = __ldg((const float2*)(memory + id.w) + p2);
            float e0 = w.x*v0.x; e0 = fmaf(w.y, v1.x, e0);
            e0 = fmaf(w.z, v2.x, e0); e0 = fmaf(w.w, v3.x, e0);
            float e1 = w.x*v0.y; e1 = fmaf(w.y, v1.y, e1);
            e1 = fmaf(w.z, v2.y, e1); e1 = fmaf(w.w, v3.y, e1);

            uint32_t hi2;
            asm("cvt.rn.bf16x2.f32 %0, %1, %2;" : "=r"(hi2) : "f"(e1), "f"(e0));
            float fh0 = __uint_as_float(hi2 << 16);
            float fh1 = __uint_as_float(hi2 & 0xffff0000u);
            uint32_t lo2;
            asm("cvt.rn.bf16x2.f32 %0, %1, %2;" : "=r"(lo2) : "f"(e1 - fh1), "f"(e0 - fh0));

            uint32_t byte = (uint32_t)m * 512u + (uint32_t)p2 * 4u;
            byte ^= (uint32_t)(m & 7) << 4;
            *(uint32_t*)(smem + SM_AHI + byte) = hi2;
            *(uint32_t*)(smem + SM_ALO + byte) = lo2;
        }
    }
    __syncthreads();

    // ---- stage 3: HMMA GEMM1 (3-pass hi/lo) + fused GEMM2 projection ----
    // warp (mw, nw): mw = wid&1 -> M rows [mw*32, +32); nw = wid>>1 -> 32 cols
    const int mw = wid & 1;
    const int nw = wid >> 1;
    const int m0 = mw * 32;

    float p[4][4];
    #pragma unroll
    for (int i = 0; i < 4; i++)
        #pragma unroll
        for (int j = 0; j < 4; j++) p[i][j] = 0.0f;

    #pragma unroll
    for (int nc = 0; nc < 2; nc++) {
        const int nb = nc * 128 + nw * 32;   // global col base for this warp
        float acc[2][4][4];
        #pragma unroll
        for (int mt = 0; mt < 2; mt++)
            #pragma unroll
            for (int nt = 0; nt < 4; nt++)
                #pragma unroll
                for (int d = 0; d < 4; d++) acc[mt][nt][d] = 0.0f;

        for (int kk = 0; kk < 16; kk++) {
            uint4 bfr[4];
            #pragma unroll
            for (int nt = 0; nt < 4; nt++) {
                const int nn = (nb >> 3) + nt;
                bfr[nt] = __ldg(&g_w1b[(kk * 32 + nn) * 32 + lane]);
            }
            #pragma unroll
            for (int mt = 0; mt < 2; mt++) {
                const int jm = lane >> 3;
                const int mrow = m0 + mt * 16 + (lane & 7) + (jm & 1) * 8;
                const int kcol = kk * 16 + (jm >> 1) * 8;
                uint32_t byte = (uint32_t)mrow * 512u + (uint32_t)kcol * 2u;
                byte ^= (uint32_t)(mrow & 7) << 4;
                uint32_t ah[4], al[4];
                ldmatrix_x4(ah[0], ah[1], ah[2], ah[3], sb + SM_AHI + byte);
                ldmatrix_x4(al[0], al[1], al[2], al[3], sb + SM_ALO + byte);
                #pragma unroll
                for (int nt = 0; nt < 4; nt++) {
                    mma_bf16(acc[mt][nt], ah, bfr[nt].x, bfr[nt].y);  // Ah*Bh
                    mma_bf16(acc[mt][nt], ah, bfr[nt].z, bfr[nt].w);  // Ah*Bl
                    mma_bf16(acc[mt][nt], al, bfr[nt].x, bfr[nt].y);  // Al*Bh
                }
            }
        }

        // chunk epilogue: tanh(d + b1) projected through W2 into p
        #pragma unroll
        for (int mt = 0; mt < 2; mt++)
            #pragma unroll
            for (int nt = 0; nt < 4; nt++)
                #pragma unroll
                for (int d = 0; d < 4; d++) {
                    const int col = nb + nt * 8 + (lane & 3) * 2 + (d & 1);
                    float h = fast_tanh(acc[mt][nt][d] + b1s[col]);
                    float4 w2 = w2s[col];
                    const int slot = mt * 2 + (d >> 1);
                    p[slot][0] = fmaf(h, w2.x, p[slot][0]);
                    p[slot][1] = fmaf(h, w2.y, p[slot][1]);
                    p[slot][2] = fmaf(h, w2.z, p[slot][2]);
                    p[slot][3] = fmaf(h, w2.w, p[slot][3]);
                }
    }

    // reduce the 4 lanes sharing the same rows (lane^1, lane^2)
    #pragma unroll
    for (int m = 1; m <= 2; m <<= 1)
        #pragma unroll
        for (int i = 0; i < 4; i++)
            #pragma unroll
            for (int j = 0; j < 4; j++)
                p[i][j] += __shfl_xor_sync(0xffffffffu, p[i][j], m);

    if ((lane & 3) == 0) {
        #pragma unroll
        for (int slot = 0; slot < 4; slot++) {
            const int mt = slot >> 1, rh = slot & 1;
            const int row = m0 + mt * 16 + (lane >> 2) + 8 * rh;
            s_part[nw * 64 + row] =
                make_float4(p[slot][0], p[slot][1], p[slot][2], p[slot][3]);
        }
    }
    __syncthreads();

    // ---- stage 4: final combine + output (threads 0..63, one M-row each) ----
    if (tid < ROWS) {
        float4 a0 = s_part[0 * 64 + tid];
        float4 a1 = s_part[1 * 64 + tid];
        float4 a2 = s_part[2 * 64 + tid];
        float4 a3 = s_part[3 * 64 + tid];
        float v0 = a0.x + a1.x + a2.x + a3.x;
        float v1 = a0.y + a1.y + a2.y + a3.y;
        float v2 = a0.z + a1.z + a2.z + a3.z;
        float v3 = a0.w + a1.w + a2.w + a3.w;
        const int qi = tid >> 3, s = tid & 7;
        const float sx = s_spt[tid*2 + 0], sy = s_spt[tid*2 + 1];
        float4 bb = __ldg((const float4*)b2);
        float4 o;
        o.x = SSCALE * fast_tanh(v0 + bb.x) + sx;
        o.y = SSCALE * fast_tanh(v1 + bb.y) + sy;
        o.z = SSCALE * fast_tanh(v2 + bb.z) + sx;
        o.w = SSCALE * fast_tanh(v3 + bb.w) + sy;
        *(float4*)(out + (size_t)(bq0 + qi) * 32 + s * 4) = o;
    }
}

extern "C" void kernel_launch(void* const* d_in, const int* in_sizes, int n_in,
                              void* d_out, int out_size)
{
    const float* ref_polys  = (const float*)d_in[0];
    const int*   ref_levels = (const int*  )d_in[1];
    const float* memory     = (const float*)d_in[2];
    const float* W1         = (const float*)d_in[3];
    const float* b1         = (const float*)d_in[4];
    const float* W2         = (const float*)d_in[5];
    const float* b2         = (const float*)d_in[6];
    float* out = (float*)d_out;

    cudaFuncSetAttribute(decoder_kernel,
                         cudaFuncAttributeMaxDynamicSharedMemorySize, SM_TOTAL);

    prep_w1<<<256, 256>>>(W1);
    decoder_kernel<<<(B_ * Q_) / QPB, 256, SM_TOTAL>>>(
        ref_polys, ref_levels, memory, b1, W2, b2, out);
}

// round 8
// speedup vs baseline: 4.9766x; 1.6022x over previous
#include <cuda_runtime.h>
#include <cuda_fp16.h>
#include <cstdint>

#define B_     8
#define Q_     500
#define C_     256
#define S_     8
#define QPB    8
#define ROWS   64           // QPB * S_
#define NPIX_  8500
#define SSCALE 0.077f

// dynamic smem layout (bytes)
#define SM_A     0          // 64 x 256 fp16 = 32768
#define SM_IDX   32768      // 64*4 int   = 1024
#define SM_WB    33792      // 64*4 float = 1024
#define SM_SPT   34816      // 64*2 float = 512
#define SM_B1    35328      // 256 float  = 1024
#define SM_W2    36352      // 256 float4 = 4096
#define SM_PART  40448      // 4 x 64 float4 = 4096
#define SM_TOTAL 44544

__constant__ int c_lvl_h[4]  = {80, 40, 20, 10};
__constant__ int c_lvl_st[4] = {0, 6400, 8000, 8400};

// W1 pre-packed into mma.sync fp16 B-fragment order:
// uint2 per (k16 chunk kk, n8 tile nn, lane): {b0, b1}
__device__ __align__(8) uint2 g_w1b[16 * 32 * 32];

__device__ __forceinline__ float fast_tanh(float x) {
    float y; asm("tanh.approx.f32 %0, %1;" : "=f"(y) : "f"(x)); return y;
}
__device__ __forceinline__ uint32_t smem_u32(const void* p) {
    uint32_t a;
    asm("{ .reg .u64 t; cvta.to.shared.u64 t, %1; cvt.u32.u64 %0, t; }" : "=r"(a) : "l"(p));
    return a;
}
__device__ __forceinline__ void ldmatrix_x4(uint32_t& r0, uint32_t& r1,
                                            uint32_t& r2, uint32_t& r3, uint32_t addr) {
    asm volatile("ldmatrix.sync.aligned.m8n8.x4.shared.b16 {%0,%1,%2,%3}, [%4];"
                 : "=r"(r0), "=r"(r1), "=r"(r2), "=r"(r3) : "r"(addr));
}
__device__ __forceinline__ void mma_f16(float* d, const uint32_t* a,
                                        uint32_t b0, uint32_t b1) {
    asm volatile("mma.sync.aligned.m16n8k16.row.col.f32.f16.f16.f32 "
                 "{%0,%1,%2,%3}, {%4,%5,%6,%7}, {%8,%9}, {%0,%1,%2,%3};"
                 : "+f"(d[0]), "+f"(d[1]), "+f"(d[2]), "+f"(d[3])
                 : "r"(a[0]), "r"(a[1]), "r"(a[2]), "r"(a[3]), "r"(b0), "r"(b1));
}

// ---- prep: W1 fp32 [K=256][N=256] -> fp16 B-fragment order -------------------
__global__ void prep_w1(const float* __restrict__ W1) {
    const int k = blockIdx.x;    // K row
    const int n = threadIdx.x;   // N col
    float v = __ldg(W1 + k * 256 + n);
    __half hv = __float2half_rn(v);

    const int kk = k >> 4, kr = k & 15;
    const int nn = n >> 3, ncell = n & 7;
    const int lane = ncell * 4 + ((kr & 7) >> 1);
    const int r = kr >> 3;       // which reg (k rows 0-7 vs 8-15)
    const int h = kr & 1;        // halfword within reg
    uint16_t* dst = (uint16_t*)g_w1b;
    const int entry = ((kk * 32 + nn) * 32 + lane);
    dst[entry * 4 + r * 2 + h] = *(uint16_t*)&hv;
}

// ---- main --------------------------------------------------------------------
__global__ __launch_bounds__(256, 3)
void decoder_kernel(const float* __restrict__ ref_polys,
                    const int*   __restrict__ ref_levels,
                    const float* __restrict__ memory,
                    const float* __restrict__ b1,
                    const float* __restrict__ W2,
                    const float* __restrict__ b2,
                    float* __restrict__ out)
{
    extern __shared__ __align__(16) char smem[];
    const uint32_t sb = smem_u32(smem);
    const int tid  = threadIdx.x;
    const int wid  = tid >> 5;
    const int lane = tid & 31;
    const int bq0  = blockIdx.x * QPB;

    int*    s_idx  = (int*)   (smem + SM_IDX);
    float*  s_w    = (float*) (smem + SM_WB);
    float*  s_spt  = (float*) (smem + SM_SPT);
    float*  b1s    = (float*) (smem + SM_B1);
    float4* w2s    = (float4*)(smem + SM_W2);
    float4* s_part = (float4*)(smem + SM_PART);

    // ---- stage 1: sampling points + bilinear corners (threads 0..63) ----
    if (tid < ROWS) {
        const int qi = tid >> 3, s = tid & 7;
        const int bq = bq0 + qi;
        const int b  = bq / Q_;
        const float lam = (float)s * (1.0f / 7.0f);
        const float* rp = ref_polys + (size_t)bq * 8;
        float px = ((rp[0]*lam + rp[1])*lam + rp[2])*lam + rp[3];
        float py = ((rp[4]*lam + rp[5])*lam + rp[6])*lam + rp[7];
        float sx = 2.0f*(px - 0.5f), sy = 2.0f*(py - 0.5f);
        s_spt[tid*2 + 0] = sx;
        s_spt[tid*2 + 1] = sy;

        const int lvl = ref_levels[bq];
        const int H = c_lvl_h[lvl], W = H;
        const int base = b * NPIX_ + c_lvl_st[lvl];
        float gx = (sx + 1.0f) * 0.5f * (float)W - 0.5f;
        float gy = (sy + 1.0f) * 0.5f * (float)H - 0.5f;
        float x0 = floorf(gx), y0 = floorf(gy);
        float wx1 = gx - x0, wx0 = 1.0f - wx1;
        float wy1 = gy - y0, wy0 = 1.0f - wy1;
        #pragma unroll
        for (int k = 0; k < 4; k++) {
            float xf = (k & 1) ? (x0 + 1.0f) : x0;
            float yf = (k & 2) ? (y0 + 1.0f) : y0;
            float wx = (k & 1) ? wx1 : wx0;
            float wy = (k & 2) ? wy1 : wy0;
            bool valid = (xf >= 0.0f) && (xf <= (float)(W-1)) &&
                         (yf >= 0.0f) && (yf <= (float)(H-1));
            int xc = (int)fminf(fmaxf(xf, 0.0f), (float)(W-1));
            int yc = (int)fminf(fmaxf(yf, 0.0f), (float)(H-1));
            s_idx[tid*4 + k] = (base + yc * W + xc) * C_;
            s_w[tid*4 + k]   = valid ? (wy * wx) : 0.0f;
        }
    }
    b1s[tid] = __ldg(b1 + tid);
    w2s[tid] = __ldg((const float4*)W2 + tid);
    __syncthreads();

    // ---- stage 2: gather -> A fp16 tile, XOR-swizzled rows of 512B ----
    {
        const int p2   = tid & 127;     // channel pair 0..127
        const int half = tid >> 7;      // row half
        #pragma unroll 4
        for (int r = 0; r < 32; r++) {
            const int m = half * 32 + r;
            int4   id = *(const int4*  )(s_idx + m * 4);
            float4 w  = *(const float4*)(s_w   + m * 4);
            float2 v0 = __ldg((const float2*)(memory + id.x) + p2);
            float2 v1 = __ldg((const float2*)(memory + id.y) + p2);
            float2 v2 = __ldg((const float2*)(memory + id.z) + p2);
            float2 v3 = __ldg((const float2*)(memory + id.w) + p2);
            float e0 = w.x*v0.x; e0 = fmaf(w.y, v1.x, e0);
            e0 = fmaf(w.z, v2.x, e0); e0 = fmaf(w.w, v3.x, e0);
            float e1 = w.x*v0.y; e1 = fmaf(w.y, v1.y, e1);
            e1 = fmaf(w.z, v2.y, e1); e1 = fmaf(w.w, v3.y, e1);

            uint32_t h2;
            asm("cvt.rn.f16x2.f32 %0, %1, %2;" : "=r"(h2) : "f"(e1), "f"(e0));

            uint32_t byte = (uint32_t)m * 512u + (uint32_t)p2 * 4u;
            byte ^= (uint32_t)(m & 7) << 4;
            *(uint32_t*)(smem + SM_A + byte) = h2;
        }
    }
    __syncthreads();

    // ---- stage 3: fp16 HMMA GEMM1 + fused GEMM2 projection ----
    // warp (mw, nw): mw = wid&1 -> M rows [mw*32, +32); nw = wid>>1 -> 32 cols
    const int mw = wid & 1;
    const int nw = wid >> 1;
    const int m0 = mw * 32;

    float p[4][4];
    #pragma unroll
    for (int i = 0; i < 4; i++)
        #pragma unroll
        for (int j = 0; j < 4; j++) p[i][j] = 0.0f;

    #pragma unroll
    for (int nc = 0; nc < 2; nc++) {
        const int nb = nc * 128 + nw * 32;   // global col base for this warp
        float acc[2][4][4];
        #pragma unroll
        for (int mt = 0; mt < 2; mt++)
            #pragma unroll
            for (int nt = 0; nt < 4; nt++)
                #pragma unroll
                for (int d = 0; d < 4; d++) acc[mt][nt][d] = 0.0f;

        #pragma unroll 2
        for (int kk = 0; kk < 16; kk++) {
            uint2 bfr[4];
            #pragma unroll
            for (int nt = 0; nt < 4; nt++) {
                const int nn = (nb >> 3) + nt;
                bfr[nt] = __ldg(&g_w1b[(kk * 32 + nn) * 32 + lane]);
            }
            #pragma unroll
            for (int mt = 0; mt < 2; mt++) {
                const int jm = lane >> 3;
                const int mrow = m0 + mt * 16 + (lane & 7) + (jm & 1) * 8;
                const int kcol = kk * 16 + (jm >> 1) * 8;
                uint32_t byte = (uint32_t)mrow * 512u + (uint32_t)kcol * 2u;
                byte ^= (uint32_t)(mrow & 7) << 4;
                uint32_t af[4];
                ldmatrix_x4(af[0], af[1], af[2], af[3], sb + SM_A + byte);
                #pragma unroll
                for (int nt = 0; nt < 4; nt++)
                    mma_f16(acc[mt][nt], af, bfr[nt].x, bfr[nt].y);
            }
        }

        // chunk epilogue: tanh(d + b1) projected through W2 into p
        #pragma unroll
        for (int mt = 0; mt < 2; mt++)
            #pragma unroll
            for (int nt = 0; nt < 4; nt++)
                #pragma unroll
                for (int d = 0; d < 4; d++) {
                    const int col = nb + nt * 8 + (lane & 3) * 2 + (d & 1);
                    float h = fast_tanh(acc[mt][nt][d] + b1s[col]);
                    float4 w2 = w2s[col];
                    const int slot = mt * 2 + (d >> 1);
                    p[slot][0] = fmaf(h, w2.x, p[slot][0]);
                    p[slot][1] = fmaf(h, w2.y, p[slot][1]);
                    p[slot][2] = fmaf(h, w2.z, p[slot][2]);
                    p[slot][3] = fmaf(h, w2.w, p[slot][3]);
                }
    }

    // reduce the 4 lanes sharing the same rows (lane^1, lane^2)
    #pragma unroll
    for (int m = 1; m <= 2; m <<= 1)
        #pragma unroll
        for (int i = 0; i < 4; i++)
            #pragma unroll
            for (int j = 0; j < 4; j++)
                p[i][j] += __shfl_xor_sync(0xffffffffu, p[i][j], m);

    if ((lane & 3) == 0) {
        #pragma unroll
        for (int slot = 0; slot < 4; slot++) {
            const int mt = slot >> 1, rh = slot & 1;
            const int row = m0 + mt * 16 + (lane >> 2) + 8 * rh;
            s_part[nw * 64 + row] =
                make_float4(p[slot][0], p[slot][1], p[slot][2], p[slot][3]);
        }
    }
    __syncthreads();

    // ---- stage 4: final combine + output (threads 0..63, one M-row each) ----
    if (tid < ROWS) {
        float4 a0 = s_part[0 * 64 + tid];
        float4 a1 = s_part[1 * 64 + tid];
        float4 a2 = s_part[2 * 64 + tid];
        float4 a3 = s_part[3 * 64 + tid];
        float v0 = a0.x + a1.x + a2.x + a3.x;
        float v1 = a0.y + a1.y + a2.y + a3.y;
        float v2 = a0.z + a1.z + a2.z + a3.z;
        float v3 = a0.w + a1.w + a2.w + a3.w;
        const int qi = tid >> 3, s = tid & 7;
        const float sx = s_spt[tid*2 + 0], sy = s_spt[tid*2 + 1];
        float4 bb = __ldg((const float4*)b2);
        float4 o;
        o.x = SSCALE * fast_tanh(v0 + bb.x) + sx;
        o.y = SSCALE * fast_tanh(v1 + bb.y) + sy;
        o.z = SSCALE * fast_tanh(v2 + bb.z) + sx;
        o.w = SSCALE * fast_tanh(v3 + bb.w) + sy;
        *(float4*)(out + (size_t)(bq0 + qi) * 32 + s * 4) = o;
    }
}

extern "C" void kernel_launch(void* const* d_in, const int* in_sizes, int n_in,
                              void* d_out, int out_size)
{
    const float* ref_polys  = (const float*)d_in[0];
    const int*   ref_levels = (const int*  )d_in[1];
    const float* memory     = (const float*)d_in[2];
    const float* W1         = (const float*)d_in[3];
    const float* b1         = (const float*)d_in[4];
    const float* W2         = (const float*)d_in[5];
    const float* b2         = (const float*)d_in[6];
    float* out = (float*)d_out;

    prep_w1<<<256, 256>>>(W1);
    decoder_kernel<<<(B_ * Q_) / QPB, 256, SM_TOTAL>>>(
        ref_polys, ref_levels, memory, b1, W2, b2, out);
}